// round 3
// baseline (speedup 1.0000x reference)
#include <cuda_runtime.h>

// ---------------------------------------------------------------------------
// DeepGRL: 3-layer GCN on GB300.
//   edge dtype probe -> deg/dinv -> CSR build -> [GEMM -> gather-agg(+BN
//   stats) -> BN fin]x2 -> GEMM(64) -> gather-agg -> d_out
// ---------------------------------------------------------------------------

#define N_ 50000
#define E_ 600000

// Scratch (static device globals; no allocation allowed).
__device__ __align__(16) int   g_deg[N_];
__device__ __align__(16) int   g_fill[N_];
__device__ __align__(16) int   g_rp[N_ + 1];
__device__ __align__(16) int   g_col[E_];
__device__ __align__(16) float g_nv[E_];
__device__ __align__(16) float g_dinv[N_];
__device__ __align__(16) float g_h1[(size_t)N_ * 128];   // GEMM outputs
__device__ __align__(16) float g_h2[(size_t)N_ * 128];   // agg outputs (pre-BN)
__device__ __align__(16) float g_sum[128];
__device__ __align__(16) float g_sq[128];
__device__ __align__(16) float g_scale[128];
__device__ __align__(16) float g_shift[128];
__device__ int g_is64;

// ---------------------------------------------------------------------------
// Detect whether the edge_index buffer is int64 or int32.
// int64 little-endian with values in [0, 2^31): every odd 32-bit word (high
// half) of the first 512 entries is 0. int32: odd words are random node ids.
__global__ void detect_kernel(const int* __restrict__ w) {
    if (threadIdx.x == 0) {
        int orv = 0;
        #pragma unroll 8
        for (int i = 0; i < 512; i++) orv |= w[2 * i + 1];
        g_is64 = (orv == 0) ? 1 : 0;
    }
}

__device__ __forceinline__ int edge_at(const void* ei, long long idx) {
    if (g_is64) return (int)((const long long*)ei)[idx];
    return ((const int*)ei)[idx];
}

// ---------------------------------------------------------------------------
__global__ void init_kernel() {
    int i = blockIdx.x * blockDim.x + threadIdx.x;
    if (i < N_) { g_deg[i] = 1; g_fill[i] = 0; }   // self-loop counts as 1
    if (i < 128) { g_sum[i] = 0.f; g_sq[i] = 0.f; }
}

__global__ void degree_kernel(const void* __restrict__ ei) {
    int e = blockIdx.x * blockDim.x + threadIdx.x;
    if (e < E_) {
        int d = edge_at(ei, (long long)E_ + e);
        if ((unsigned)d < (unsigned)N_) atomicAdd(&g_deg[d], 1);
    }
}

__global__ void dinv_kernel() {
    int i = blockIdx.x * blockDim.x + threadIdx.x;
    if (i < N_) g_dinv[i] = rsqrtf((float)g_deg[i]);   // deg >= 1 always
}

// Single-block exclusive scan of (deg-1) -> g_rp. 1024 threads, shfl scans.
__global__ void scan_kernel() {
    __shared__ int wsum[32];
    __shared__ int s_carry;
    int tid = threadIdx.x;
    int lane = tid & 31, w = tid >> 5;
    if (tid == 0) s_carry = 0;
    __syncthreads();
    for (int base = 0; base < N_; base += 1024) {
        int i = base + tid;
        int v = (i < N_) ? (g_deg[i] - 1) : 0;
        int x = v;
        #pragma unroll
        for (int o = 1; o < 32; o <<= 1) {
            int t = __shfl_up_sync(0xffffffffu, x, o);
            if (lane >= o) x += t;
        }
        if (lane == 31) wsum[w] = x;
        __syncthreads();
        if (w == 0) {
            int y = wsum[lane];
            #pragma unroll
            for (int o = 1; o < 32; o <<= 1) {
                int t = __shfl_up_sync(0xffffffffu, y, o);
                if (lane >= o) y += t;
            }
            wsum[lane] = y;
        }
        __syncthreads();
        int incl = x + (w > 0 ? wsum[w - 1] : 0);
        int c = s_carry;
        if (i < N_) g_rp[i] = c + incl - v;   // exclusive
        __syncthreads();
        if (tid == 1023) s_carry = c + incl;
        __syncthreads();
    }
    if (tid == 0) g_rp[N_] = s_carry;   // == E_
}

__global__ void scatter_kernel(const void* __restrict__ ei) {
    int e = blockIdx.x * blockDim.x + threadIdx.x;
    if (e < E_) {
        int s = edge_at(ei, e);
        int d = edge_at(ei, (long long)E_ + e);
        if ((unsigned)s < (unsigned)N_ && (unsigned)d < (unsigned)N_) {
            int pos = g_rp[d] + atomicAdd(&g_fill[d], 1);
            if ((unsigned)pos < (unsigned)E_) {
                g_col[pos] = s;
                g_nv[pos] = g_dinv[s] * g_dinv[d];
            }
        }
    }
}

// BN finalize: scale = g * rsqrt(var+eps); shift = be - mean*scale. Zero stats.
__global__ void bnfin_kernel(const float* __restrict__ g, const float* __restrict__ be) {
    int f = threadIdx.x;
    const float invn = 1.0f / (float)N_;
    float m = g_sum[f] * invn;
    float v = g_sq[f] * invn - m * m;
    float sc = g[f] * rsqrtf(v + 1e-5f);
    g_scale[f] = sc;
    g_shift[f] = be[f] - m * sc;
    g_sum[f] = 0.f; g_sq[f] = 0.f;
}

// ---------------------------------------------------------------------------
// GEMM: C[M,BN] = act(A[M,128]) @ W[128,BN]. BM=64, BK=32, static smem only.
// 256 threads = 16(tx) x 16(ty); thread tile 4 rows x (BN/16) cols.
// ---------------------------------------------------------------------------
template<int BN, int ACT, int SRC>
__global__ __launch_bounds__(256)
void gemm_kernel(const float* __restrict__ Ain, const float* __restrict__ W) {
    __shared__ float sA[32][68];        // [k][m], padded
    __shared__ float sW[32][BN + 4];    // [k][n], padded
    __shared__ float s_scale[128], s_shift[128];

    const float* A = (SRC == 0) ? Ain : g_h2;
    float* C = g_h1;
    int tid = threadIdx.x;

    if (ACT && tid < 128) { s_scale[tid] = g_scale[tid]; s_shift[tid] = g_shift[tid]; }
    __syncthreads();

    const int row0 = blockIdx.x * 64;
    const int tx = tid & 15, ty = tid >> 4;
    const int TN = BN / 16;

    float acc[4][TN];
    #pragma unroll
    for (int i = 0; i < 4; i++)
        #pragma unroll
        for (int j = 0; j < TN; j++) acc[i][j] = 0.f;

    #pragma unroll
    for (int ks = 0; ks < 4; ks++) {
        const int k0 = ks * 32;

        // Load A tile (64 rows x 32 k), fused BN+ReLU if ACT. 2 float4 / thread.
        #pragma unroll
        for (int h = 0; h < 2; h++) {
            int t = tid + h * 256;
            int r = t >> 3;            // 0..63
            int c = (t & 7) * 4;       // 0..28
            float4 v = make_float4(0.f, 0.f, 0.f, 0.f);
            int gr = row0 + r;
            if (gr < N_) v = *(const float4*)(A + (size_t)gr * 128 + k0 + c);
            if (ACT) {
                v.x = fmaxf(fmaf(v.x, s_scale[k0 + c + 0], s_shift[k0 + c + 0]), 0.f);
                v.y = fmaxf(fmaf(v.y, s_scale[k0 + c + 1], s_shift[k0 + c + 1]), 0.f);
                v.z = fmaxf(fmaf(v.z, s_scale[k0 + c + 2], s_shift[k0 + c + 2]), 0.f);
                v.w = fmaxf(fmaf(v.w, s_scale[k0 + c + 3], s_shift[k0 + c + 3]), 0.f);
            }
            sA[c + 0][r] = v.x;
            sA[c + 1][r] = v.y;
            sA[c + 2][r] = v.z;
            sA[c + 3][r] = v.w;
        }

        // Load W tile (32 k x BN).
        #pragma unroll
        for (int h = 0; h < (32 * BN / 4) / 256; h++) {
            int t = tid + h * 256;
            int k = t / (BN / 4);
            int c = (t % (BN / 4)) * 4;
            float4 v = *(const float4*)(W + (size_t)(k0 + k) * BN + c);
            *(float4*)(&sW[k][c]) = v;
        }
        __syncthreads();

        #pragma unroll
        for (int k = 0; k < 32; k++) {
            float a[4];
            #pragma unroll
            for (int i = 0; i < 4; i++) a[i] = sA[k][ty * 4 + i];
            float b[TN];
            #pragma unroll
            for (int j = 0; j < TN; j += 4) {
                float4 bv = *(const float4*)(&sW[k][tx * TN + j]);
                b[j + 0] = bv.x; b[j + 1] = bv.y; b[j + 2] = bv.z; b[j + 3] = bv.w;
            }
            #pragma unroll
            for (int i = 0; i < 4; i++)
                #pragma unroll
                for (int j = 0; j < TN; j++)
                    acc[i][j] = fmaf(a[i], b[j], acc[i][j]);
        }
        __syncthreads();
    }

    #pragma unroll
    for (int i = 0; i < 4; i++) {
        int r = row0 + ty * 4 + i;
        if (r < N_) {
            #pragma unroll
            for (int j = 0; j < TN; j += 4) {
                float4 v = make_float4(acc[i][j], acc[i][j + 1], acc[i][j + 2], acc[i][j + 3]);
                *(float4*)(C + (size_t)r * BN + tx * TN + j) = v;
            }
        }
    }
}

// ---------------------------------------------------------------------------
// Gather aggregation: out[i] = bias + dinv_i^2 * h[i] + sum_p nv[p]*h[col[p]].
// One warp per row (grid-strided). Optional fused BN statistics.
// ---------------------------------------------------------------------------
template<int F, int STATS, int OUTP>
__global__ __launch_bounds__(256)
void agg_kernel(const float* __restrict__ bias, float* __restrict__ outp) {
    __shared__ float s_sum[128], s_sq[128];
    const float* __restrict__ h = g_h1;
    float* out = (OUTP == 0) ? g_h2 : outp;
    int tid = threadIdx.x;
    if (STATS) {
        if (tid < 128) { s_sum[tid] = 0.f; s_sq[tid] = 0.f; }
        __syncthreads();
    }
    int lane = tid & 31;
    int gw = (blockIdx.x * 256 + tid) >> 5;
    int nw = (gridDim.x * 256) >> 5;

    if (F == 128) {
        float4 bv = *(const float4*)(bias + lane * 4);
        for (int row = gw; row < N_; row += nw) {
            float di = g_dinv[row];
            float w0 = di * di;
            float4 a = *(const float4*)(h + (size_t)row * 128 + lane * 4);
            float4 acc;
            acc.x = w0 * a.x; acc.y = w0 * a.y; acc.z = w0 * a.z; acc.w = w0 * a.w;
            int p = g_rp[row], pe = g_rp[row + 1];
            for (; p + 1 < pe; p += 2) {
                int c0 = g_col[p], c1 = g_col[p + 1];
                float u0 = g_nv[p], u1 = g_nv[p + 1];
                float4 h0 = *(const float4*)(h + (size_t)c0 * 128 + lane * 4);
                float4 h1 = *(const float4*)(h + (size_t)c1 * 128 + lane * 4);
                acc.x = fmaf(u0, h0.x, fmaf(u1, h1.x, acc.x));
                acc.y = fmaf(u0, h0.y, fmaf(u1, h1.y, acc.y));
                acc.z = fmaf(u0, h0.z, fmaf(u1, h1.z, acc.z));
                acc.w = fmaf(u0, h0.w, fmaf(u1, h1.w, acc.w));
            }
            if (p < pe) {
                int c0 = g_col[p];
                float u0 = g_nv[p];
                float4 h0 = *(const float4*)(h + (size_t)c0 * 128 + lane * 4);
                acc.x = fmaf(u0, h0.x, acc.x);
                acc.y = fmaf(u0, h0.y, acc.y);
                acc.z = fmaf(u0, h0.z, acc.z);
                acc.w = fmaf(u0, h0.w, acc.w);
            }
            acc.x += bv.x; acc.y += bv.y; acc.z += bv.z; acc.w += bv.w;
            *(float4*)(out + (size_t)row * 128 + lane * 4) = acc;
            if (STATS) {
                int c = lane * 4;
                atomicAdd(&s_sum[c + 0], acc.x); atomicAdd(&s_sq[c + 0], acc.x * acc.x);
                atomicAdd(&s_sum[c + 1], acc.y); atomicAdd(&s_sq[c + 1], acc.y * acc.y);
                atomicAdd(&s_sum[c + 2], acc.z); atomicAdd(&s_sq[c + 2], acc.z * acc.z);
                atomicAdd(&s_sum[c + 3], acc.w); atomicAdd(&s_sq[c + 3], acc.w * acc.w);
            }
        }
        if (STATS) {
            __syncthreads();
            if (tid < 128) {
                atomicAdd(&g_sum[tid], s_sum[tid]);
                atomicAdd(&g_sq[tid], s_sq[tid]);
            }
        }
    } else {  // F == 64 (final layer, no stats)
        float2 bv = *(const float2*)(bias + lane * 2);
        for (int row = gw; row < N_; row += nw) {
            float di = g_dinv[row];
            float w0 = di * di;
            float2 a = *(const float2*)(h + (size_t)row * 64 + lane * 2);
            float2 acc;
            acc.x = w0 * a.x; acc.y = w0 * a.y;
            int p = g_rp[row], pe = g_rp[row + 1];
            for (; p + 1 < pe; p += 2) {
                int c0 = g_col[p], c1 = g_col[p + 1];
                float u0 = g_nv[p], u1 = g_nv[p + 1];
                float2 h0 = *(const float2*)(h + (size_t)c0 * 64 + lane * 2);
                float2 h1 = *(const float2*)(h + (size_t)c1 * 64 + lane * 2);
                acc.x = fmaf(u0, h0.x, fmaf(u1, h1.x, acc.x));
                acc.y = fmaf(u0, h0.y, fmaf(u1, h1.y, acc.y));
            }
            if (p < pe) {
                int c0 = g_col[p];
                float u0 = g_nv[p];
                float2 h0 = *(const float2*)(h + (size_t)c0 * 64 + lane * 2);
                acc.x = fmaf(u0, h0.x, acc.x);
                acc.y = fmaf(u0, h0.y, acc.y);
            }
            acc.x += bv.x; acc.y += bv.y;
            *(float2*)(out + (size_t)row * 64 + lane * 2) = acc;
        }
    }
}

// ---------------------------------------------------------------------------
extern "C" void kernel_launch(void* const* d_in, const int* in_sizes, int n_in,
                              void* d_out, int out_size) {
    const float* x   = (const float*)d_in[0];
    const void*  ei  = d_in[1];
    const float* W1  = (const float*)d_in[2];
    const float* b1  = (const float*)d_in[3];
    const float* g1  = (const float*)d_in[4];
    const float* be1 = (const float*)d_in[5];
    const float* W2  = (const float*)d_in[6];
    const float* b2  = (const float*)d_in[7];
    const float* g2  = (const float*)d_in[8];
    const float* be2 = (const float*)d_in[9];
    const float* W3  = (const float*)d_in[10];
    const float* b3  = (const float*)d_in[11];
    float*       out = (float*)d_out;

    const int nb = (N_ + 255) / 256;
    const int eb = (E_ + 255) / 256;
    const int gb = (N_ + 63) / 64;
    const int ab = 1184;   // grid-strided warps for aggregation

    detect_kernel<<<1, 32>>>((const int*)ei);
    init_kernel<<<nb, 256>>>();
    degree_kernel<<<eb, 256>>>(ei);
    dinv_kernel<<<nb, 256>>>();
    scan_kernel<<<1, 1024>>>();
    scatter_kernel<<<eb, 256>>>(ei);

    // Layer 1
    gemm_kernel<128, 0, 0><<<gb, 256>>>(x, W1);
    agg_kernel<128, 1, 0><<<ab, 256>>>(b1, nullptr);
    bnfin_kernel<<<1, 128>>>(g1, be1);
    // Layer 2
    gemm_kernel<128, 1, 1><<<gb, 256>>>(nullptr, W2);
    agg_kernel<128, 1, 0><<<ab, 256>>>(b2, nullptr);
    bnfin_kernel<<<1, 128>>>(g2, be2);
    // Layer 3
    gemm_kernel<64, 1, 1><<<gb, 256>>>(nullptr, W3);
    agg_kernel<64, 0, 1><<<ab, 256>>>(b3, out);
}

// round 4
// speedup vs baseline: 1.2179x; 1.2179x over previous
#include <cuda_runtime.h>

// ---------------------------------------------------------------------------
// DeepGRL 3-layer GCN on GB300.
// init(+dtype probe) -> degree -> scan(+dinv) -> scatter ->
//   [GEMM(f32x2, fused BN from stats) -> gather-agg(+stats)] x3 -> d_out
// ---------------------------------------------------------------------------

#define N_ 50000
#define E_ 600000

typedef unsigned long long ull;

__device__ __align__(16) int   g_deg[N_];
__device__ __align__(16) int   g_fill[N_];
__device__ __align__(16) int   g_rp[N_ + 1];
__device__ __align__(16) int   g_col[E_];
__device__ __align__(16) float g_nv[E_];
__device__ __align__(16) float g_dinv[N_];
__device__ __align__(16) float g_h1[(size_t)N_ * 128];   // GEMM outputs
__device__ __align__(16) float g_h2[(size_t)N_ * 128];   // agg outputs (pre-BN)
__device__ __align__(16) float g_stsum[2][128];
__device__ __align__(16) float g_stsq[2][128];
__device__ int g_is64;

// ---------------------------------------------------------------------------
// init + edge-dtype probe (block 0). int64 => all odd 32-bit words of the
// first 512 entries are zero.
__global__ void init_kernel(const int* __restrict__ w) {
    int i = blockIdx.x * blockDim.x + threadIdx.x;
    if (i < N_) { g_deg[i] = 1; g_fill[i] = 0; }
    if (blockIdx.x == 1 && threadIdx.x < 128) {
        g_stsum[0][threadIdx.x] = 0.f; g_stsq[0][threadIdx.x] = 0.f;
        g_stsum[1][threadIdx.x] = 0.f; g_stsq[1][threadIdx.x] = 0.f;
    }
    if (blockIdx.x == 0) {
        __shared__ int sor;
        if (threadIdx.x == 0) sor = 0;
        __syncthreads();
        int v = w[2 * threadIdx.x + 1] | w[2 * (threadIdx.x + 256) + 1];
        if (v) atomicOr(&sor, 1);
        __syncthreads();
        if (threadIdx.x == 0) g_is64 = (sor == 0) ? 1 : 0;
    }
}

__device__ __forceinline__ int edge_at(const void* ei, long long idx) {
    if (g_is64) return (int)((const long long*)ei)[idx];
    return ((const int*)ei)[idx];
}

__global__ void degree_kernel(const void* __restrict__ ei) {
    int e = blockIdx.x * blockDim.x + threadIdx.x;
    if (e < E_) {
        int d = edge_at(ei, (long long)E_ + e);
        if ((unsigned)d < (unsigned)N_) atomicAdd(&g_deg[d], 1);
    }
}

// Single-block exclusive scan of (deg-1) -> g_rp; also writes g_dinv.
__global__ void scan_kernel() {
    __shared__ int wsum[32];
    __shared__ int s_carry;
    int tid = threadIdx.x;
    int lane = tid & 31, w = tid >> 5;
    if (tid == 0) s_carry = 0;
    __syncthreads();
    for (int base = 0; base < N_; base += 1024) {
        int i = base + tid;
        int dg = (i < N_) ? g_deg[i] : 1;
        if (i < N_) g_dinv[i] = rsqrtf((float)dg);
        int v = dg - 1;
        int x = v;
        #pragma unroll
        for (int o = 1; o < 32; o <<= 1) {
            int t = __shfl_up_sync(0xffffffffu, x, o);
            if (lane >= o) x += t;
        }
        if (lane == 31) wsum[w] = x;
        __syncthreads();
        if (w == 0) {
            int y = wsum[lane];
            #pragma unroll
            for (int o = 1; o < 32; o <<= 1) {
                int t = __shfl_up_sync(0xffffffffu, y, o);
                if (lane >= o) y += t;
            }
            wsum[lane] = y;
        }
        __syncthreads();
        int incl = x + (w > 0 ? wsum[w - 1] : 0);
        int c = s_carry;
        if (i < N_) g_rp[i] = c + incl - v;
        __syncthreads();
        if (tid == 1023) s_carry = c + incl;
        __syncthreads();
    }
    if (tid == 0) g_rp[N_] = s_carry;
}

__global__ void scatter_kernel(const void* __restrict__ ei) {
    int e = blockIdx.x * blockDim.x + threadIdx.x;
    if (e < E_) {
        int s = edge_at(ei, e);
        int d = edge_at(ei, (long long)E_ + e);
        if ((unsigned)s < (unsigned)N_ && (unsigned)d < (unsigned)N_) {
            int pos = g_rp[d] + atomicAdd(&g_fill[d], 1);
            if ((unsigned)pos < (unsigned)E_) {
                g_col[pos] = s;
                g_nv[pos] = g_dinv[s] * g_dinv[d];
            }
        }
    }
}

// ---------------------------------------------------------------------------
// GEMM: C[M,BN] = act(A[M,128]) @ W[128,BN]. BM=128, BK=32.
// f32x2 packed accumulation across N (4 or 2 pairs x 8 rows per thread).
// ACT: BN scale/shift computed per block from double-buffered stats (folded
// bnfin). 256 threads: tx=tid&15 (8 cols), ty=tid>>4 (8 rows).
// ---------------------------------------------------------------------------
__device__ __forceinline__ void ffma2(ull &d, ull a, ull b) {
    asm("fma.rn.f32x2 %0, %1, %2, %0;" : "+l"(d) : "l"(a), "l"(b));
}
__device__ __forceinline__ ull dup2(float a) {
    ull r;
    asm("mov.b64 %0, {%1, %1};" : "=l"(r) : "r"(__float_as_uint(a)));
    return r;
}

template<int BN, int ACT, int SIDX>
__global__ __launch_bounds__(256, 2)
void gemm_kernel(const float* __restrict__ Ain, const float* __restrict__ W,
                 const float* __restrict__ gam, const float* __restrict__ bet) {
    __shared__ float sA[32][136];       // [k][m], 16B-aligned rows
    __shared__ float sW[32][BN + 4];    // [k][n]
    __shared__ float s_scale[128], s_shift[128];

    const float* A = ACT ? (const float*)g_h2 : Ain;
    float* C = g_h1;
    const int tid = threadIdx.x;

    if (ACT && tid < 128) {
        const float invn = 1.0f / (float)N_;
        float m = g_stsum[SIDX][tid] * invn;
        float v = g_stsq[SIDX][tid] * invn - m * m;
        float sc = gam[tid] * rsqrtf(v + 1e-5f);
        s_scale[tid] = sc;
        s_shift[tid] = bet[tid] - m * sc;
    }
    if (ACT) __syncthreads();

    const int row0 = blockIdx.x * 128;
    const int tx = tid & 15, ty = tid >> 4;
    const int NP = BN / 32;             // ull pairs per thread (4 or 2)

    ull acc[8][NP];
    #pragma unroll
    for (int i = 0; i < 8; i++)
        #pragma unroll
        for (int j = 0; j < NP; j++) acc[i][j] = 0ull;

    #pragma unroll
    for (int ks = 0; ks < 4; ks++) {
        const int k0 = ks * 32;

        // A tile: 128 rows x 32 k, fused BN+ReLU. 4 float4 per thread.
        #pragma unroll
        for (int h = 0; h < 4; h++) {
            int t = tid + h * 256;
            int r = t >> 3;            // 0..127
            int c = (t & 7) * 4;       // 0..28
            float4 v = make_float4(0.f, 0.f, 0.f, 0.f);
            int gr = row0 + r;
            if (gr < N_) v = *(const float4*)(A + (size_t)gr * 128 + k0 + c);
            if (ACT) {
                v.x = fmaxf(fmaf(v.x, s_scale[k0 + c + 0], s_shift[k0 + c + 0]), 0.f);
                v.y = fmaxf(fmaf(v.y, s_scale[k0 + c + 1], s_shift[k0 + c + 1]), 0.f);
                v.z = fmaxf(fmaf(v.z, s_scale[k0 + c + 2], s_shift[k0 + c + 2]), 0.f);
                v.w = fmaxf(fmaf(v.w, s_scale[k0 + c + 3], s_shift[k0 + c + 3]), 0.f);
            }
            sA[c + 0][r] = v.x;
            sA[c + 1][r] = v.y;
            sA[c + 2][r] = v.z;
            sA[c + 3][r] = v.w;
        }

        // W tile: 32 k x BN.
        #pragma unroll
        for (int h = 0; h < (32 * BN / 4) / 256; h++) {
            int t = tid + h * 256;
            int k = t / (BN / 4);
            int c = (t % (BN / 4)) * 4;
            *(float4*)(&sW[k][c]) = *(const float4*)(W + (size_t)(k0 + k) * BN + c);
        }
        __syncthreads();

        #pragma unroll 4
        for (int k = 0; k < 32; k++) {
            float4 a0 = *(const float4*)(&sA[k][ty * 8]);
            float4 a1 = *(const float4*)(&sA[k][ty * 8 + 4]);
            ull av[8];
            av[0] = dup2(a0.x); av[1] = dup2(a0.y);
            av[2] = dup2(a0.z); av[3] = dup2(a0.w);
            av[4] = dup2(a1.x); av[5] = dup2(a1.y);
            av[6] = dup2(a1.z); av[7] = dup2(a1.w);
            ull bv[NP];
            #pragma unroll
            for (int j = 0; j < NP; j += 2) {
                ulonglong2 b = *(const ulonglong2*)(&sW[k][tx * (2 * NP) + 2 * j]);
                bv[j] = b.x; bv[j + 1] = b.y;
            }
            #pragma unroll
            for (int i = 0; i < 8; i++)
                #pragma unroll
                for (int j = 0; j < NP; j++)
                    ffma2(acc[i][j], av[i], bv[j]);
        }
        __syncthreads();
    }

    #pragma unroll
    for (int i = 0; i < 8; i++) {
        int r = row0 + ty * 8 + i;
        if (r < N_) {
            #pragma unroll
            for (int j = 0; j < NP; j += 2) {
                float4 v;
                v.x = __uint_as_float((unsigned)(acc[i][j] & 0xffffffffull));
                v.y = __uint_as_float((unsigned)(acc[i][j] >> 32));
                v.z = __uint_as_float((unsigned)(acc[i][j + 1] & 0xffffffffull));
                v.w = __uint_as_float((unsigned)(acc[i][j + 1] >> 32));
                *(float4*)(C + (size_t)r * BN + tx * (2 * NP) + 2 * j) = v;
            }
        }
    }
}

// ---------------------------------------------------------------------------
// Gather aggregation: out[i] = bias + dinv_i^2 * h[i] + sum_p nv[p]*h[col[p]].
// One warp per row (grid-strided). Optional fused BN statistics into SIDX.
// ---------------------------------------------------------------------------
template<int F, int STATS, int SIDX, int OUTP>
__global__ __launch_bounds__(256)
void agg_kernel(const float* __restrict__ bias, float* __restrict__ outp) {
    __shared__ float s_sum[128], s_sq[128];
    const float* __restrict__ h = g_h1;
    float* out = (OUTP == 0) ? g_h2 : outp;
    int tid = threadIdx.x;
    if (STATS) {
        if (tid < 128) { s_sum[tid] = 0.f; s_sq[tid] = 0.f; }
        __syncthreads();
    }
    int lane = tid & 31;
    int gw = (blockIdx.x * 256 + tid) >> 5;
    int nw = (gridDim.x * 256) >> 5;

    if (F == 128) {
        float4 bv = *(const float4*)(bias + lane * 4);
        for (int row = gw; row < N_; row += nw) {
            float di = g_dinv[row];
            float w0 = di * di;
            float4 a = *(const float4*)(h + (size_t)row * 128 + lane * 4);
            float4 acc;
            acc.x = w0 * a.x; acc.y = w0 * a.y; acc.z = w0 * a.z; acc.w = w0 * a.w;
            int p = g_rp[row], pe = g_rp[row + 1];
            for (; p + 1 < pe; p += 2) {
                int c0 = g_col[p], c1 = g_col[p + 1];
                float u0 = g_nv[p], u1 = g_nv[p + 1];
                float4 h0 = *(const float4*)(h + (size_t)c0 * 128 + lane * 4);
                float4 h1 = *(const float4*)(h + (size_t)c1 * 128 + lane * 4);
                acc.x = fmaf(u0, h0.x, fmaf(u1, h1.x, acc.x));
                acc.y = fmaf(u0, h0.y, fmaf(u1, h1.y, acc.y));
                acc.z = fmaf(u0, h0.z, fmaf(u1, h1.z, acc.z));
                acc.w = fmaf(u0, h0.w, fmaf(u1, h1.w, acc.w));
            }
            if (p < pe) {
                int c0 = g_col[p];
                float u0 = g_nv[p];
                float4 h0 = *(const float4*)(h + (size_t)c0 * 128 + lane * 4);
                acc.x = fmaf(u0, h0.x, acc.x);
                acc.y = fmaf(u0, h0.y, acc.y);
                acc.z = fmaf(u0, h0.z, acc.z);
                acc.w = fmaf(u0, h0.w, acc.w);
            }
            acc.x += bv.x; acc.y += bv.y; acc.z += bv.z; acc.w += bv.w;
            *(float4*)(out + (size_t)row * 128 + lane * 4) = acc;
            if (STATS) {
                int c = lane * 4;
                atomicAdd(&s_sum[c + 0], acc.x); atomicAdd(&s_sq[c + 0], acc.x * acc.x);
                atomicAdd(&s_sum[c + 1], acc.y); atomicAdd(&s_sq[c + 1], acc.y * acc.y);
                atomicAdd(&s_sum[c + 2], acc.z); atomicAdd(&s_sq[c + 2], acc.z * acc.z);
                atomicAdd(&s_sum[c + 3], acc.w); atomicAdd(&s_sq[c + 3], acc.w * acc.w);
            }
        }
        if (STATS) {
            __syncthreads();
            if (tid < 128) {
                atomicAdd(&g_stsum[SIDX][tid], s_sum[tid]);
                atomicAdd(&g_stsq[SIDX][tid], s_sq[tid]);
            }
        }
    } else {  // F == 64 (final layer)
        float2 bv = *(const float2*)(bias + lane * 2);
        for (int row = gw; row < N_; row += nw) {
            float di = g_dinv[row];
            float w0 = di * di;
            float2 a = *(const float2*)(h + (size_t)row * 64 + lane * 2);
            float2 acc;
            acc.x = w0 * a.x; acc.y = w0 * a.y;
            int p = g_rp[row], pe = g_rp[row + 1];
            for (; p + 1 < pe; p += 2) {
                int c0 = g_col[p], c1 = g_col[p + 1];
                float u0 = g_nv[p], u1 = g_nv[p + 1];
                float2 h0 = *(const float2*)(h + (size_t)c0 * 64 + lane * 2);
                float2 h1 = *(const float2*)(h + (size_t)c1 * 64 + lane * 2);
                acc.x = fmaf(u0, h0.x, fmaf(u1, h1.x, acc.x));
                acc.y = fmaf(u0, h0.y, fmaf(u1, h1.y, acc.y));
            }
            if (p < pe) {
                int c0 = g_col[p];
                float u0 = g_nv[p];
                float2 h0 = *(const float2*)(h + (size_t)c0 * 64 + lane * 2);
                acc.x = fmaf(u0, h0.x, acc.x);
                acc.y = fmaf(u0, h0.y, acc.y);
            }
            acc.x += bv.x; acc.y += bv.y;
            *(float2*)(out + (size_t)row * 64 + lane * 2) = acc;
        }
    }
}

// ---------------------------------------------------------------------------
extern "C" void kernel_launch(void* const* d_in, const int* in_sizes, int n_in,
                              void* d_out, int out_size) {
    const float* x   = (const float*)d_in[0];
    const void*  ei  = d_in[1];
    const float* W1  = (const float*)d_in[2];
    const float* b1  = (const float*)d_in[3];
    const float* g1  = (const float*)d_in[4];
    const float* be1 = (const float*)d_in[5];
    const float* W2  = (const float*)d_in[6];
    const float* b2  = (const float*)d_in[7];
    const float* g2  = (const float*)d_in[8];
    const float* be2 = (const float*)d_in[9];
    const float* W3  = (const float*)d_in[10];
    const float* b3  = (const float*)d_in[11];
    float*       out = (float*)d_out;

    const int nb = (N_ + 255) / 256;
    const int eb = (E_ + 255) / 256;
    const int gb = (N_ + 127) / 128;
    const int ab = 1184;

    init_kernel<<<nb, 256>>>((const int*)ei);
    degree_kernel<<<eb, 256>>>(ei);
    scan_kernel<<<1, 1024>>>();
    scatter_kernel<<<eb, 256>>>(ei);

    // Layer 1
    gemm_kernel<128, 0, 0><<<gb, 256>>>(x, W1, nullptr, nullptr);
    agg_kernel<128, 1, 0, 0><<<ab, 256>>>(b1, nullptr);
    // Layer 2 (BN from stats[0] folded into GEMM prologue)
    gemm_kernel<128, 1, 0><<<gb, 256>>>(nullptr, W2, g1, be1);
    agg_kernel<128, 1, 1, 0><<<ab, 256>>>(b2, nullptr);
    // Layer 3 (BN from stats[1])
    gemm_kernel<64, 1, 1><<<gb, 256>>>(nullptr, W3, g2, be2);
    agg_kernel<64, 0, 0, 1><<<ab, 256>>>(b3, out);
}

// round 5
// speedup vs baseline: 1.3563x; 1.1136x over previous
#include <cuda_runtime.h>

// ---------------------------------------------------------------------------
// DeepGRL 3-layer GCN on GB300.
// detect -> degree(fill) -> scanA/B/C (rp,dinv, zero fill) -> scatter(col) ->
//   [GEMM(f32x2, fused BN) -> gather-agg(+stats, on-the-fly norm)] x3 -> out
// Invariants restored each call: g_fill == 0, g_stsum/g_stsq == 0.
// ---------------------------------------------------------------------------

#define N_ 50000
#define E_ 600000
#define NB_ 196          // scan blocks: 196*256 >= N_

typedef unsigned long long ull;

__device__ __align__(16) int   g_fill[NB_ * 256];    // zero at call start
__device__ __align__(16) int   g_part[NB_];
__device__ __align__(16) int   g_rp[N_ + 1];
__device__ __align__(16) int   g_col[E_];
__device__ __align__(16) float g_dinv[N_];
__device__ __align__(16) float g_h1[(size_t)N_ * 128];
__device__ __align__(16) float g_h2[(size_t)N_ * 128];
__device__ __align__(16) float g_stsum[2][128];      // zero at call start
__device__ __align__(16) float g_stsq[2][128];
__device__ int g_is64;

// ---------------------------------------------------------------------------
__global__ void detect_kernel(const int* __restrict__ w) {
    __shared__ int sor;
    if (threadIdx.x == 0) sor = 0;
    __syncthreads();
    int v = w[2 * threadIdx.x + 1] | w[2 * (threadIdx.x + 256) + 1];
    if (v) atomicOr(&sor, 1);
    __syncthreads();
    if (threadIdx.x == 0) g_is64 = (sor == 0) ? 1 : 0;
}

__device__ __forceinline__ int edge_at(const void* ei, long long idx) {
    if (g_is64) return (int)((const long long*)ei)[idx];
    return ((const int*)ei)[idx];
}

__global__ void degree_kernel(const void* __restrict__ ei) {
    int e = blockIdx.x * blockDim.x + threadIdx.x;
    if (e < E_) {
        int d = edge_at(ei, (long long)E_ + e);
        if ((unsigned)d < (unsigned)N_) atomicAdd(&g_fill[d], 1);
    }
}

// scanA: per-block sums of g_fill (edge counts w/o self-loops).
__global__ __launch_bounds__(256) void scanA_kernel() {
    __shared__ int ws[8];
    int i = blockIdx.x * 256 + threadIdx.x;
    int v = (i < N_) ? g_fill[i] : 0;
    int lane = threadIdx.x & 31, w = threadIdx.x >> 5;
    int x = v;
    #pragma unroll
    for (int o = 16; o > 0; o >>= 1) x += __shfl_down_sync(0xffffffffu, x, o);
    if (lane == 0) ws[w] = x;
    __syncthreads();
    if (threadIdx.x < 8) {
        int y = ws[threadIdx.x];
        #pragma unroll
        for (int o = 4; o > 0; o >>= 1) y += __shfl_down_sync(0xffu, y, o);
        if (threadIdx.x == 0) g_part[blockIdx.x] = y;
    }
}

// scanB: exclusive scan of NB_ partials (single block).
__global__ __launch_bounds__(256) void scanB_kernel() {
    __shared__ int ws[8];
    int t = threadIdx.x;
    int v = (t < NB_) ? g_part[t] : 0;
    int lane = t & 31, w = t >> 5;
    int x = v;
    #pragma unroll
    for (int o = 1; o < 32; o <<= 1) {
        int q = __shfl_up_sync(0xffffffffu, x, o);
        if (lane >= o) x += q;
    }
    if (lane == 31) ws[w] = x;
    __syncthreads();
    if (w == 0 && lane < 8) {
        int y = ws[lane];
        #pragma unroll
        for (int o = 1; o < 8; o <<= 1) {
            int q = __shfl_up_sync(0xffu, y, o);
            if (lane >= o) y += q;
        }
        ws[lane] = y;
    }
    __syncthreads();
    int excl = x - v + (w > 0 ? ws[w - 1] : 0);
    if (t < NB_) g_part[t] = excl;
}

// scanC: rp = global exclusive prefix; dinv = rsqrt(deg); zero g_fill.
__global__ __launch_bounds__(256) void scanC_kernel() {
    __shared__ int ws[8];
    int i = blockIdx.x * 256 + threadIdx.x;
    int v = (i < N_) ? g_fill[i] : 0;
    int lane = threadIdx.x & 31, w = threadIdx.x >> 5;
    int x = v;
    #pragma unroll
    for (int o = 1; o < 32; o <<= 1) {
        int q = __shfl_up_sync(0xffffffffu, x, o);
        if (lane >= o) x += q;
    }
    if (lane == 31) ws[w] = x;
    __syncthreads();
    if (w == 0 && lane < 8) {
        int y = ws[lane];
        #pragma unroll
        for (int o = 1; o < 8; o <<= 1) {
            int q = __shfl_up_sync(0xffu, y, o);
            if (lane >= o) y += q;
        }
        ws[lane] = y;
    }
    __syncthreads();
    int excl = g_part[blockIdx.x] + x - v + (w > 0 ? ws[w - 1] : 0);
    if (i < N_) {
        g_rp[i] = excl;
        g_dinv[i] = rsqrtf((float)(v + 1));
        g_fill[i] = 0;
        if (i == N_ - 1) g_rp[N_] = excl + v;
    }
}

__global__ void scatter_kernel(const void* __restrict__ ei) {
    int e = blockIdx.x * blockDim.x + threadIdx.x;
    if (e < E_) {
        int s = edge_at(ei, e);
        int d = edge_at(ei, (long long)E_ + e);
        if ((unsigned)s < (unsigned)N_ && (unsigned)d < (unsigned)N_) {
            int pos = g_rp[d] + atomicAdd(&g_fill[d], 1);
            if ((unsigned)pos < (unsigned)E_) g_col[pos] = s;
        }
    }
}

// ---------------------------------------------------------------------------
// GEMM: C[M,BN] = act(A[M,128]) @ W[128,BN]. BM=128, BK=32, f32x2 packed.
// ---------------------------------------------------------------------------
__device__ __forceinline__ void ffma2(ull &d, ull a, ull b) {
    asm("fma.rn.f32x2 %0, %1, %2, %0;" : "+l"(d) : "l"(a), "l"(b));
}
__device__ __forceinline__ ull dup2(float a) {
    ull r;
    asm("mov.b64 %0, {%1, %1};" : "=l"(r) : "r"(__float_as_uint(a)));
    return r;
}

template<int BN, int ACT, int SIDX>
__global__ __launch_bounds__(256, 2)
void gemm_kernel(const float* __restrict__ Ain, const float* __restrict__ W,
                 const float* __restrict__ gam, const float* __restrict__ bet) {
    __shared__ float sA[32][136];
    __shared__ float sW[32][BN + 4];
    __shared__ float s_scale[128], s_shift[128];

    const float* A = ACT ? (const float*)g_h2 : Ain;
    float* C = g_h1;
    const int tid = threadIdx.x;

    if (ACT && tid < 128) {
        const float invn = 1.0f / (float)N_;
        float m = g_stsum[SIDX][tid] * invn;
        float v = g_stsq[SIDX][tid] * invn - m * m;
        float sc = gam[tid] * rsqrtf(v + 1e-5f);
        s_scale[tid] = sc;
        s_shift[tid] = bet[tid] - m * sc;
    }
    if (ACT) __syncthreads();

    const int row0 = blockIdx.x * 128;
    const int tx = tid & 15, ty = tid >> 4;
    const int NP = BN / 32;

    ull acc[8][NP];
    #pragma unroll
    for (int i = 0; i < 8; i++)
        #pragma unroll
        for (int j = 0; j < NP; j++) acc[i][j] = 0ull;

    #pragma unroll
    for (int ks = 0; ks < 4; ks++) {
        const int k0 = ks * 32;

        #pragma unroll
        for (int h = 0; h < 4; h++) {
            int t = tid + h * 256;
            int r = t >> 3;
            int c = (t & 7) * 4;
            float4 v = make_float4(0.f, 0.f, 0.f, 0.f);
            int gr = row0 + r;
            if (gr < N_) v = *(const float4*)(A + (size_t)gr * 128 + k0 + c);
            if (ACT) {
                v.x = fmaxf(fmaf(v.x, s_scale[k0 + c + 0], s_shift[k0 + c + 0]), 0.f);
                v.y = fmaxf(fmaf(v.y, s_scale[k0 + c + 1], s_shift[k0 + c + 1]), 0.f);
                v.z = fmaxf(fmaf(v.z, s_scale[k0 + c + 2], s_shift[k0 + c + 2]), 0.f);
                v.w = fmaxf(fmaf(v.w, s_scale[k0 + c + 3], s_shift[k0 + c + 3]), 0.f);
            }
            sA[c + 0][r] = v.x;
            sA[c + 1][r] = v.y;
            sA[c + 2][r] = v.z;
            sA[c + 3][r] = v.w;
        }

        #pragma unroll
        for (int h = 0; h < (32 * BN / 4) / 256; h++) {
            int t = tid + h * 256;
            int k = t / (BN / 4);
            int c = (t % (BN / 4)) * 4;
            *(float4*)(&sW[k][c]) = *(const float4*)(W + (size_t)(k0 + k) * BN + c);
        }
        __syncthreads();

        #pragma unroll 4
        for (int k = 0; k < 32; k++) {
            float4 a0 = *(const float4*)(&sA[k][ty * 8]);
            float4 a1 = *(const float4*)(&sA[k][ty * 8 + 4]);
            ull av[8];
            av[0] = dup2(a0.x); av[1] = dup2(a0.y);
            av[2] = dup2(a0.z); av[3] = dup2(a0.w);
            av[4] = dup2(a1.x); av[5] = dup2(a1.y);
            av[6] = dup2(a1.z); av[7] = dup2(a1.w);
            ull bv[NP];
            #pragma unroll
            for (int j = 0; j < NP; j += 2) {
                ulonglong2 b = *(const ulonglong2*)(&sW[k][tx * (2 * NP) + 2 * j]);
                bv[j] = b.x; bv[j + 1] = b.y;
            }
            #pragma unroll
            for (int i = 0; i < 8; i++)
                #pragma unroll
                for (int j = 0; j < NP; j++)
                    ffma2(acc[i][j], av[i], bv[j]);
        }
        __syncthreads();
    }

    #pragma unroll
    for (int i = 0; i < 8; i++) {
        int r = row0 + ty * 8 + i;
        if (r < N_) {
            #pragma unroll
            for (int j = 0; j < NP; j += 2) {
                float4 v;
                v.x = __uint_as_float((unsigned)(acc[i][j] & 0xffffffffull));
                v.y = __uint_as_float((unsigned)(acc[i][j] >> 32));
                v.z = __uint_as_float((unsigned)(acc[i][j + 1] & 0xffffffffull));
                v.w = __uint_as_float((unsigned)(acc[i][j + 1] >> 32));
                *(float4*)(C + (size_t)r * BN + tx * (2 * NP) + 2 * j) = v;
            }
        }
    }
}

// ---------------------------------------------------------------------------
// Gather aggregation, norm on the fly: u = dinv[col]*dinv[row].
// out[i] = bias + dinv_i^2*h[i] + sum u*h[col]. Warp per row, 4-edge unroll.
// CLEAN: 0 none, 1 zero stats[0], 2 zero stats[1] + g_fill.
// ---------------------------------------------------------------------------
template<int F, int STATS, int SIDX, int OUTP, int CLEAN>
__global__ __launch_bounds__(256)
void agg_kernel(const float* __restrict__ bias, float* __restrict__ outp) {
    __shared__ float s_sum[128], s_sq[128];
    const float* __restrict__ h = g_h1;
    const float* __restrict__ dv = g_dinv;
    const int* __restrict__ cols = g_col;
    float* out = (OUTP == 0) ? g_h2 : outp;
    int tid = threadIdx.x;
    if (STATS) {
        if (tid < 128) { s_sum[tid] = 0.f; s_sq[tid] = 0.f; }
        __syncthreads();
    }
    if (CLEAN == 1 && blockIdx.x == 0 && tid < 128) {
        g_stsum[0][tid] = 0.f; g_stsq[0][tid] = 0.f;
    }
    if (CLEAN == 2 && blockIdx.x == 0 && tid < 128) {
        g_stsum[1][tid] = 0.f; g_stsq[1][tid] = 0.f;
    }
    int lane = tid & 31;
    int gw = (blockIdx.x * 256 + tid) >> 5;
    int nw = (gridDim.x * 256) >> 5;

    if (F == 128) {
        float4 bv = *(const float4*)(bias + lane * 4);
        for (int row = gw; row < N_; row += nw) {
            float dr = dv[row];
            float w0 = dr * dr;
            if (CLEAN == 2 && lane == 0) g_fill[row] = 0;
            float4 a = *(const float4*)(h + (size_t)row * 128 + lane * 4);
            float4 acc;
            acc.x = w0 * a.x; acc.y = w0 * a.y; acc.z = w0 * a.z; acc.w = w0 * a.w;
            int p = g_rp[row], pe = g_rp[row + 1];
            for (; p + 4 <= pe; p += 4) {
                int c0 = cols[p], c1 = cols[p + 1], c2 = cols[p + 2], c3 = cols[p + 3];
                float u0 = dv[c0] * dr, u1 = dv[c1] * dr;
                float u2 = dv[c2] * dr, u3 = dv[c3] * dr;
                float4 h0 = *(const float4*)(h + (size_t)c0 * 128 + lane * 4);
                float4 h1 = *(const float4*)(h + (size_t)c1 * 128 + lane * 4);
                float4 h2 = *(const float4*)(h + (size_t)c2 * 128 + lane * 4);
                float4 h3 = *(const float4*)(h + (size_t)c3 * 128 + lane * 4);
                acc.x = fmaf(u0, h0.x, acc.x); acc.y = fmaf(u0, h0.y, acc.y);
                acc.z = fmaf(u0, h0.z, acc.z); acc.w = fmaf(u0, h0.w, acc.w);
                acc.x = fmaf(u1, h1.x, acc.x); acc.y = fmaf(u1, h1.y, acc.y);
                acc.z = fmaf(u1, h1.z, acc.z); acc.w = fmaf(u1, h1.w, acc.w);
                acc.x = fmaf(u2, h2.x, acc.x); acc.y = fmaf(u2, h2.y, acc.y);
                acc.z = fmaf(u2, h2.z, acc.z); acc.w = fmaf(u2, h2.w, acc.w);
                acc.x = fmaf(u3, h3.x, acc.x); acc.y = fmaf(u3, h3.y, acc.y);
                acc.z = fmaf(u3, h3.z, acc.z); acc.w = fmaf(u3, h3.w, acc.w);
            }
            for (; p < pe; p++) {
                int c0 = cols[p];
                float u0 = dv[c0] * dr;
                float4 h0 = *(const float4*)(h + (size_t)c0 * 128 + lane * 4);
                acc.x = fmaf(u0, h0.x, acc.x); acc.y = fmaf(u0, h0.y, acc.y);
                acc.z = fmaf(u0, h0.z, acc.z); acc.w = fmaf(u0, h0.w, acc.w);
            }
            acc.x += bv.x; acc.y += bv.y; acc.z += bv.z; acc.w += bv.w;
            *(float4*)(out + (size_t)row * 128 + lane * 4) = acc;
            if (STATS) {
                int c = lane * 4;
                atomicAdd(&s_sum[c + 0], acc.x); atomicAdd(&s_sq[c + 0], acc.x * acc.x);
                atomicAdd(&s_sum[c + 1], acc.y); atomicAdd(&s_sq[c + 1], acc.y * acc.y);
                atomicAdd(&s_sum[c + 2], acc.z); atomicAdd(&s_sq[c + 2], acc.z * acc.z);
                atomicAdd(&s_sum[c + 3], acc.w); atomicAdd(&s_sq[c + 3], acc.w * acc.w);
            }
        }
        if (STATS) {
            __syncthreads();
            if (tid < 128) {
                atomicAdd(&g_stsum[SIDX][tid], s_sum[tid]);
                atomicAdd(&g_stsq[SIDX][tid], s_sq[tid]);
            }
        }
    } else {  // F == 64
        float2 bv = *(const float2*)(bias + lane * 2);
        for (int row = gw; row < N_; row += nw) {
            float dr = dv[row];
            float w0 = dr * dr;
            if (CLEAN == 2 && lane == 0) g_fill[row] = 0;
            float2 a = *(const float2*)(h + (size_t)row * 64 + lane * 2);
            float2 acc;
            acc.x = w0 * a.x; acc.y = w0 * a.y;
            int p = g_rp[row], pe = g_rp[row + 1];
            for (; p + 4 <= pe; p += 4) {
                int c0 = cols[p], c1 = cols[p + 1], c2 = cols[p + 2], c3 = cols[p + 3];
                float u0 = dv[c0] * dr, u1 = dv[c1] * dr;
                float u2 = dv[c2] * dr, u3 = dv[c3] * dr;
                float2 h0 = *(const float2*)(h + (size_t)c0 * 64 + lane * 2);
                float2 h1 = *(const float2*)(h + (size_t)c1 * 64 + lane * 2);
                float2 h2 = *(const float2*)(h + (size_t)c2 * 64 + lane * 2);
                float2 h3 = *(const float2*)(h + (size_t)c3 * 64 + lane * 2);
                acc.x = fmaf(u0, h0.x, acc.x); acc.y = fmaf(u0, h0.y, acc.y);
                acc.x = fmaf(u1, h1.x, acc.x); acc.y = fmaf(u1, h1.y, acc.y);
                acc.x = fmaf(u2, h2.x, acc.x); acc.y = fmaf(u2, h2.y, acc.y);
                acc.x = fmaf(u3, h3.x, acc.x); acc.y = fmaf(u3, h3.y, acc.y);
            }
            for (; p < pe; p++) {
                int c0 = cols[p];
                float u0 = dv[c0] * dr;
                float2 h0 = *(const float2*)(h + (size_t)c0 * 64 + lane * 2);
                acc.x = fmaf(u0, h0.x, acc.x); acc.y = fmaf(u0, h0.y, acc.y);
            }
            acc.x += bv.x; acc.y += bv.y;
            *(float2*)(out + (size_t)row * 64 + lane * 2) = acc;
        }
    }
}

// ---------------------------------------------------------------------------
extern "C" void kernel_launch(void* const* d_in, const int* in_sizes, int n_in,
                              void* d_out, int out_size) {
    const float* x   = (const float*)d_in[0];
    const void*  ei  = d_in[1];
    const float* W1  = (const float*)d_in[2];
    const float* b1  = (const float*)d_in[3];
    const float* g1  = (const float*)d_in[4];
    const float* be1 = (const float*)d_in[5];
    const float* W2  = (const float*)d_in[6];
    const float* b2  = (const float*)d_in[7];
    const float* g2  = (const float*)d_in[8];
    const float* be2 = (const float*)d_in[9];
    const float* W3  = (const float*)d_in[10];
    const float* b3  = (const float*)d_in[11];
    float*       out = (float*)d_out;

    const int eb = (E_ + 255) / 256;
    const int gb = (N_ + 127) / 128;
    const int ab = 1184;

    detect_kernel<<<1, 256>>>((const int*)ei);
    degree_kernel<<<eb, 256>>>(ei);
    scanA_kernel<<<NB_, 256>>>();
    scanB_kernel<<<1, 256>>>();
    scanC_kernel<<<NB_, 256>>>();
    scatter_kernel<<<eb, 256>>>(ei);

    // Layer 1
    gemm_kernel<128, 0, 0><<<gb, 256>>>(x, W1, nullptr, nullptr);
    agg_kernel<128, 1, 0, 0, 0><<<ab, 256>>>(b1, nullptr);
    // Layer 2
    gemm_kernel<128, 1, 0><<<gb, 256>>>(nullptr, W2, g1, be1);
    agg_kernel<128, 1, 1, 0, 1><<<ab, 256>>>(b2, nullptr);
    // Layer 3
    gemm_kernel<64, 1, 1><<<gb, 256>>>(nullptr, W3, g2, be2);
    agg_kernel<64, 0, 0, 1, 2><<<ab, 256>>>(b3, out);
}

// round 9
// speedup vs baseline: 1.3911x; 1.0256x over previous
#include <cuda_runtime.h>

// ---------------------------------------------------------------------------
// DeepGRL 3-layer GCN on GB300.
// fused(GEMM1 || degree) -> scanA -> scanC(prefix+dinv+zero fill) ->
//   scatter -> agg1 -> GEMM2 -> agg2 -> GEMM3 -> agg3 -> out
// 9 launches. Edge dtype probed per-block (int32 vs int64).
// Invariants restored each call: g_fill == 0, g_stsum/g_stsq == 0.
// ---------------------------------------------------------------------------

#define N_ 50000
#define E_ 600000
#define NB_ 196          // scan blocks: 196*256 >= N_
#define GB_ 391          // GEMM blocks for BM=128: ceil(50000/128)
#define EB_ 2344         // edge blocks: ceil(600000/256)

typedef unsigned long long ull;

__device__ __align__(16) int   g_fill[NB_ * 256];    // zero at call start
__device__ __align__(16) int   g_part[NB_];
__device__ __align__(16) int   g_rp[N_ + 1];
__device__ __align__(16) int   g_col[E_];
__device__ __align__(16) float g_dinv[N_];
__device__ __align__(16) float g_h1[(size_t)N_ * 128];
__device__ __align__(16) float g_h2[(size_t)N_ * 128];
__device__ __align__(16) float g_stsum[2][128];      // zero at call start
__device__ __align__(16) float g_stsq[2][128];

// ---------------------------------------------------------------------------
// Per-block edge-dtype probe: int64 layout => odd 32-bit words of the first
// 512 entries are all zero. Reads are L2-hot after the first block.
__device__ __forceinline__ int probe_is64(const int* __restrict__ w, int tid) {
    __shared__ int s_or;
    if (tid == 0) s_or = 0;
    __syncthreads();
    int v = w[2 * tid + 1] | w[2 * (tid + 256) + 1];
    if (__any_sync(0xffffffffu, v != 0) && (tid & 31) == 0) atomicOr(&s_or, 1);
    __syncthreads();
    return s_or == 0;
}

__device__ __forceinline__ int edge_at(const void* ei, int is64, long long idx) {
    if (is64) return (int)((const long long*)ei)[idx];
    return ((const int*)ei)[idx];
}

// ---------------------------------------------------------------------------
// f32x2 helpers.
__device__ __forceinline__ void ffma2(ull &d, ull a, ull b) {
    asm("fma.rn.f32x2 %0, %1, %2, %0;" : "+l"(d) : "l"(a), "l"(b));
}
__device__ __forceinline__ ull dup2(float a) {
    ull r;
    asm("mov.b64 %0, {%1, %1};" : "=l"(r) : "r"(__float_as_uint(a)));
    return r;
}

// GEMM body: C[row0:row0+128, BN] = act(A) @ W. BK=32, f32x2 packed over N.
template<int BN, int ACT, int SIDX>
__device__ __forceinline__ void gemm_body(const float* __restrict__ A,
                                          const float* __restrict__ W,
                                          const float* __restrict__ gam,
                                          const float* __restrict__ bet,
                                          int row0) {
    __shared__ float sA[32][136];
    __shared__ float sW[32][BN + 4];
    __shared__ float s_scale[128], s_shift[128];

    float* C = g_h1;
    const int tid = threadIdx.x;

    if (ACT && tid < 128) {
        const float invn = 1.0f / (float)N_;
        float m = g_stsum[SIDX][tid] * invn;
        float v = g_stsq[SIDX][tid] * invn - m * m;
        float sc = gam[tid] * rsqrtf(v + 1e-5f);
        s_scale[tid] = sc;
        s_shift[tid] = bet[tid] - m * sc;
    }
    if (ACT) __syncthreads();

    const int tx = tid & 15, ty = tid >> 4;
    const int NP = BN / 32;

    ull acc[8][NP > 0 ? NP : 1];
    #pragma unroll
    for (int i = 0; i < 8; i++)
        #pragma unroll
        for (int j = 0; j < NP; j++) acc[i][j] = 0ull;

    #pragma unroll
    for (int ks = 0; ks < 4; ks++) {
        const int k0 = ks * 32;

        #pragma unroll
        for (int h = 0; h < 4; h++) {
            int t = tid + h * 256;
            int r = t >> 3;
            int c = (t & 7) * 4;
            float4 v = make_float4(0.f, 0.f, 0.f, 0.f);
            int gr = row0 + r;
            if (gr < N_) v = *(const float4*)(A + (size_t)gr * 128 + k0 + c);
            if (ACT) {
                v.x = fmaxf(fmaf(v.x, s_scale[k0 + c + 0], s_shift[k0 + c + 0]), 0.f);
                v.y = fmaxf(fmaf(v.y, s_scale[k0 + c + 1], s_shift[k0 + c + 1]), 0.f);
                v.z = fmaxf(fmaf(v.z, s_scale[k0 + c + 2], s_shift[k0 + c + 2]), 0.f);
                v.w = fmaxf(fmaf(v.w, s_scale[k0 + c + 3], s_shift[k0 + c + 3]), 0.f);
            }
            sA[c + 0][r] = v.x;
            sA[c + 1][r] = v.y;
            sA[c + 2][r] = v.z;
            sA[c + 3][r] = v.w;
        }

        #pragma unroll
        for (int h = 0; h < (32 * BN / 4) / 256; h++) {
            int t = tid + h * 256;
            int k = t / (BN / 4);
            int c = (t % (BN / 4)) * 4;
            *(float4*)(&sW[k][c]) = *(const float4*)(W + (size_t)(k0 + k) * BN + c);
        }
        __syncthreads();

        #pragma unroll 4
        for (int k = 0; k < 32; k++) {
            float4 a0 = *(const float4*)(&sA[k][ty * 8]);
            float4 a1 = *(const float4*)(&sA[k][ty * 8 + 4]);
            ull av[8];
            av[0] = dup2(a0.x); av[1] = dup2(a0.y);
            av[2] = dup2(a0.z); av[3] = dup2(a0.w);
            av[4] = dup2(a1.x); av[5] = dup2(a1.y);
            av[6] = dup2(a1.z); av[7] = dup2(a1.w);
            ull bv[NP > 0 ? NP : 1];
            #pragma unroll
            for (int j = 0; j < NP; j += 2) {
                ulonglong2 b = *(const ulonglong2*)(&sW[k][tx * (2 * NP) + 2 * j]);
                bv[j] = b.x; bv[j + 1] = b.y;
            }
            #pragma unroll
            for (int i = 0; i < 8; i++)
                #pragma unroll
                for (int j = 0; j < NP; j++)
                    ffma2(acc[i][j], av[i], bv[j]);
        }
        __syncthreads();
    }

    #pragma unroll
    for (int i = 0; i < 8; i++) {
        int r = row0 + ty * 8 + i;
        if (r < N_) {
            #pragma unroll
            for (int j = 0; j < NP; j += 2) {
                float4 v;
                v.x = __uint_as_float((unsigned)(acc[i][j] & 0xffffffffull));
                v.y = __uint_as_float((unsigned)(acc[i][j] >> 32));
                v.z = __uint_as_float((unsigned)(acc[i][j + 1] & 0xffffffffull));
                v.w = __uint_as_float((unsigned)(acc[i][j + 1] >> 32));
                *(float4*)(C + (size_t)r * BN + tx * (2 * NP) + 2 * j) = v;
            }
        }
    }
}

// ---------------------------------------------------------------------------
// Fused launch 1: blocks [0,GB_) run GEMM1 (x@W1); blocks [GB_,GB_+EB_)
// histogram destination degrees into g_fill.
__global__ __launch_bounds__(256, 2)
void fused1_kernel(const float* __restrict__ x, const float* __restrict__ W1,
                   const void* __restrict__ ei) {
    if (blockIdx.x < GB_) {
        gemm_body<128, 0, 0>(x, W1, nullptr, nullptr, blockIdx.x * 128);
    } else {
        int is64 = probe_is64((const int*)ei, threadIdx.x);
        int e = (blockIdx.x - GB_) * 256 + threadIdx.x;
        if (e < E_) {
            int d = edge_at(ei, is64, (long long)E_ + e);
            if ((unsigned)d < (unsigned)N_) atomicAdd(&g_fill[d], 1);
        }
    }
}

// scanA: per-block sums of g_fill.
__global__ __launch_bounds__(256) void scanA_kernel() {
    __shared__ int ws[8];
    int i = blockIdx.x * 256 + threadIdx.x;
    int v = (i < N_) ? g_fill[i] : 0;
    int lane = threadIdx.x & 31, w = threadIdx.x >> 5;
    int x = v;
    #pragma unroll
    for (int o = 16; o > 0; o >>= 1) x += __shfl_down_sync(0xffffffffu, x, o);
    if (lane == 0) ws[w] = x;
    __syncthreads();
    if (threadIdx.x < 8) {
        int y = ws[threadIdx.x];
        #pragma unroll
        for (int o = 4; o > 0; o >>= 1) y += __shfl_down_sync(0xffu, y, o);
        if (threadIdx.x == 0) g_part[blockIdx.x] = y;
    }
}

// scanC: base = sum of partials below this block (computed locally), then
// block-local exclusive scan; writes rp, dinv, zeroes g_fill.
__global__ __launch_bounds__(256) void scanC_kernel() {
    __shared__ int ws[8];
    __shared__ int s_base;
    int t = threadIdx.x;
    int lane = t & 31, w = t >> 5;

    // block base from partials
    {
        int pv = (t < NB_ && t < (int)blockIdx.x) ? g_part[t] : 0;
        int x = pv;
        #pragma unroll
        for (int o = 16; o > 0; o >>= 1) x += __shfl_down_sync(0xffffffffu, x, o);
        if (lane == 0) ws[w] = x;
        __syncthreads();
        if (t == 0) {
            int b = 0;
            #pragma unroll
            for (int i = 0; i < 8; i++) b += ws[i];
            s_base = b;
        }
        __syncthreads();
    }
    int base = s_base;
    __syncthreads();

    int i = blockIdx.x * 256 + t;
    int v = (i < N_) ? g_fill[i] : 0;
    int x = v;
    #pragma unroll
    for (int o = 1; o < 32; o <<= 1) {
        int q = __shfl_up_sync(0xffffffffu, x, o);
        if (lane >= o) x += q;
    }
    if (lane == 31) ws[w] = x;
    __syncthreads();
    if (w == 0 && lane < 8) {
        int y = ws[lane];
        #pragma unroll
        for (int o = 1; o < 8; o <<= 1) {
            int q = __shfl_up_sync(0xffu, y, o);
            if (lane >= o) y += q;
        }
        ws[lane] = y;
    }
    __syncthreads();
    int excl = base + x - v + (w > 0 ? ws[w - 1] : 0);
    if (i < N_) {
        g_rp[i] = excl;
        g_dinv[i] = rsqrtf((float)(v + 1));
        g_fill[i] = 0;
        if (i == N_ - 1) g_rp[N_] = excl + v;
    }
}

__global__ void scatter_kernel(const void* __restrict__ ei) {
    int is64 = probe_is64((const int*)ei, threadIdx.x);
    int e = blockIdx.x * blockDim.x + threadIdx.x;
    if (e < E_) {
        int s = edge_at(ei, is64, e);
        int d = edge_at(ei, is64, (long long)E_ + e);
        if ((unsigned)s < (unsigned)N_ && (unsigned)d < (unsigned)N_) {
            int pos = g_rp[d] + atomicAdd(&g_fill[d], 1);
            if ((unsigned)pos < (unsigned)E_) g_col[pos] = s;
        }
    }
}

// Standalone GEMM launches (layers 2, 3).
template<int BN, int ACT, int SIDX>
__global__ __launch_bounds__(256, 2)
void gemm_kernel(const float* __restrict__ W,
                 const float* __restrict__ gam, const float* __restrict__ bet) {
    gemm_body<BN, ACT, SIDX>((const float*)g_h2, W, gam, bet, blockIdx.x * 128);
}

// ---------------------------------------------------------------------------
// Gather aggregation, norm on the fly: u = dinv[col]*dinv[row].
// CLEAN: 0 none, 1 zero stats[0], 2 zero stats[1] + g_fill.
// ---------------------------------------------------------------------------
template<int F, int STATS, int SIDX, int OUTP, int CLEAN>
__global__ __launch_bounds__(256)
void agg_kernel(const float* __restrict__ bias, float* __restrict__ outp) {
    __shared__ float s_sum[128], s_sq[128];
    const float* __restrict__ h = g_h1;
    const float* __restrict__ dv = g_dinv;
    const int* __restrict__ cols = g_col;
    float* out = (OUTP == 0) ? g_h2 : outp;
    int tid = threadIdx.x;
    if (STATS) {
        if (tid < 128) { s_sum[tid] = 0.f; s_sq[tid] = 0.f; }
        __syncthreads();
    }
    if (CLEAN == 1 && blockIdx.x == 0 && tid < 128) {
        g_stsum[0][tid] = 0.f; g_stsq[0][tid] = 0.f;
    }
    if (CLEAN == 2 && blockIdx.x == 0 && tid < 128) {
        g_stsum[1][tid] = 0.f; g_stsq[1][tid] = 0.f;
    }
    int lane = tid & 31;
    int gw = (blockIdx.x * 256 + tid) >> 5;
    int nw = (gridDim.x * 256) >> 5;

    if (F == 128) {
        float4 bv = *(const float4*)(bias + lane * 4);
        for (int row = gw; row < N_; row += nw) {
            float dr = dv[row];
            float w0 = dr * dr;
            if (CLEAN == 2 && lane == 0) g_fill[row] = 0;
            float4 a = *(const float4*)(h + (size_t)row * 128 + lane * 4);
            float4 acc;
            acc.x = w0 * a.x; acc.y = w0 * a.y; acc.z = w0 * a.z; acc.w = w0 * a.w;
            int p = g_rp[row], pe = g_rp[row + 1];
            for (; p + 4 <= pe; p += 4) {
                int c0 = cols[p], c1 = cols[p + 1], c2 = cols[p + 2], c3 = cols[p + 3];
                float u0 = dv[c0] * dr, u1 = dv[c1] * dr;
                float u2 = dv[c2] * dr, u3 = dv[c3] * dr;
                float4 h0 = *(const float4*)(h + (size_t)c0 * 128 + lane * 4);
                float4 h1 = *(const float4*)(h + (size_t)c1 * 128 + lane * 4);
                float4 h2 = *(const float4*)(h + (size_t)c2 * 128 + lane * 4);
                float4 h3 = *(const float4*)(h + (size_t)c3 * 128 + lane * 4);
                acc.x = fmaf(u0, h0.x, acc.x); acc.y = fmaf(u0, h0.y, acc.y);
                acc.z = fmaf(u0, h0.z, acc.z); acc.w = fmaf(u0, h0.w, acc.w);
                acc.x = fmaf(u1, h1.x, acc.x); acc.y = fmaf(u1, h1.y, acc.y);
                acc.z = fmaf(u1, h1.z, acc.z); acc.w = fmaf(u1, h1.w, acc.w);
                acc.x = fmaf(u2, h2.x, acc.x); acc.y = fmaf(u2, h2.y, acc.y);
                acc.z = fmaf(u2, h2.z, acc.z); acc.w = fmaf(u2, h2.w, acc.w);
                acc.x = fmaf(u3, h3.x, acc.x); acc.y = fmaf(u3, h3.y, acc.y);
                acc.z = fmaf(u3, h3.z, acc.z); acc.w = fmaf(u3, h3.w, acc.w);
            }
            for (; p < pe; p++) {
                int c0 = cols[p];
                float u0 = dv[c0] * dr;
                float4 h0 = *(const float4*)(h + (size_t)c0 * 128 + lane * 4);
                acc.x = fmaf(u0, h0.x, acc.x); acc.y = fmaf(u0, h0.y, acc.y);
                acc.z = fmaf(u0, h0.z, acc.z); acc.w = fmaf(u0, h0.w, acc.w);
            }
            acc.x += bv.x; acc.y += bv.y; acc.z += bv.z; acc.w += bv.w;
            *(float4*)(out + (size_t)row * 128 + lane * 4) = acc;
            if (STATS) {
                int c = lane * 4;
                atomicAdd(&s_sum[c + 0], acc.x); atomicAdd(&s_sq[c + 0], acc.x * acc.x);
                atomicAdd(&s_sum[c + 1], acc.y); atomicAdd(&s_sq[c + 1], acc.y * acc.y);
                atomicAdd(&s_sum[c + 2], acc.z); atomicAdd(&s_sq[c + 2], acc.z * acc.z);
                atomicAdd(&s_sum[c + 3], acc.w); atomicAdd(&s_sq[c + 3], acc.w * acc.w);
            }
        }
        if (STATS) {
            __syncthreads();
            if (tid < 128) {
                atomicAdd(&g_stsum[SIDX][tid], s_sum[tid]);
                atomicAdd(&g_stsq[SIDX][tid], s_sq[tid]);
            }
        }
    } else {  // F == 64
        float2 bv = *(const float2*)(bias + lane * 2);
        for (int row = gw; row < N_; row += nw) {
            float dr = dv[row];
            float w0 = dr * dr;
            if (CLEAN == 2 && lane == 0) g_fill[row] = 0;
            float2 a = *(const float2*)(h + (size_t)row * 64 + lane * 2);
            float2 acc;
            acc.x = w0 * a.x; acc.y = w0 * a.y;
            int p = g_rp[row], pe = g_rp[row + 1];
            for (; p + 4 <= pe; p += 4) {
                int c0 = cols[p], c1 = cols[p + 1], c2 = cols[p + 2], c3 = cols[p + 3];
                float u0 = dv[c0] * dr, u1 = dv[c1] * dr;
                float u2 = dv[c2] * dr, u3 = dv[c3] * dr;
                float2 h0 = *(const float2*)(h + (size_t)c0 * 64 + lane * 2);
                float2 h1 = *(const float2*)(h + (size_t)c1 * 64 + lane * 2);
                float2 h2 = *(const float2*)(h + (size_t)c2 * 64 + lane * 2);
                float2 h3 = *(const float2*)(h + (size_t)c3 * 64 + lane * 2);
                acc.x = fmaf(u0, h0.x, acc.x); acc.y = fmaf(u0, h0.y, acc.y);
                acc.x = fmaf(u1, h1.x, acc.x); acc.y = fmaf(u1, h1.y, acc.y);
                acc.x = fmaf(u2, h2.x, acc.x); acc.y = fmaf(u2, h2.y, acc.y);
                acc.x = fmaf(u3, h3.x, acc.x); acc.y = fmaf(u3, h3.y, acc.y);
            }
            for (; p < pe; p++) {
                int c0 = cols[p];
                float u0 = dv[c0] * dr;
                float2 h0 = *(const float2*)(h + (size_t)c0 * 64 + lane * 2);
                acc.x = fmaf(u0, h0.x, acc.x); acc.y = fmaf(u0, h0.y, acc.y);
            }
            acc.x += bv.x; acc.y += bv.y;
            *(float2*)(out + (size_t)row * 64 + lane * 2) = acc;
        }
    }
}

// ---------------------------------------------------------------------------
extern "C" void kernel_launch(void* const* d_in, const int* in_sizes, int n_in,
                              void* d_out, int out_size) {
    const float* x   = (const float*)d_in[0];
    const void*  ei  = d_in[1];
    const float* W1  = (const float*)d_in[2];
    const float* b1  = (const float*)d_in[3];
    const float* g1  = (const float*)d_in[4];
    const float* be1 = (const float*)d_in[5];
    const float* W2  = (const float*)d_in[6];
    const float* b2  = (const float*)d_in[7];
    const float* g2  = (const float*)d_in[8];
    const float* be2 = (const float*)d_in[9];
    const float* W3  = (const float*)d_in[10];
    const float* b3  = (const float*)d_in[11];
    float*       out = (float*)d_out;

    const int ab = 1184;

    fused1_kernel<<<GB_ + EB_, 256>>>(x, W1, ei);      // GEMM1 || degree
    scanA_kernel<<<NB_, 256>>>();
    scanC_kernel<<<NB_, 256>>>();
    scatter_kernel<<<EB_, 256>>>(ei);

    agg_kernel<128, 1, 0, 0, 0><<<ab, 256>>>(b1, nullptr);
    gemm_kernel<128, 1, 0><<<GB_, 256>>>(W2, g1, be1);
    agg_kernel<128, 1, 1, 0, 1><<<ab, 256>>>(b2, nullptr);
    gemm_kernel<64, 1, 1><<<GB_, 256>>>(W3, g2, be2);
    agg_kernel<64, 0, 0, 1, 2><<<ab, 256>>>(b3, out);
}